// round 5
// baseline (speedup 1.0000x reference)
#include <cuda_runtime.h>
#include <cuda_bf16.h>
#include <cstdint>

#define Bq   8
#define Nn   1024
#define DIN  256
#define DOUT 256
#define Rr   4

// ------------------------- scratch globals ----------------------------------
__device__ __nv_bfloat16 g_xh[(size_t)Bq * Nn * DIN];
__device__ __nv_bfloat16 g_xl[(size_t)Bq * Nn * DIN];
__device__ __nv_bfloat16 g_rwh[(size_t)Rr * DOUT * DIN];
__device__ __nv_bfloat16 g_rwl[(size_t)Rr * DOUT * DIN];
__device__ float         g_feats[(size_t)Bq * Rr * Nn * DOUT];   // 32 MB
__device__ float         g_w[Bq * Rr * Nn];
__device__ float         g_invZ[Bq * Rr * Nn];
__device__ __nv_bfloat16 g_wfh[(size_t)Bq * Rr * DOUT * Nn];     // wf^T hi [br][d][m]
__device__ __nv_bfloat16 g_wfl[(size_t)Bq * Rr * DOUT * Nn];     // wf^T lo
__device__ __nv_bfloat16 g_adjbf[(size_t)Bq * Rr * Nn * Nn];     // 64 MB

// ------------------------- helpers ------------------------------------------
__device__ __forceinline__ uint32_t smem_u32(const void* p) {
    uint32_t a;
    asm("{ .reg .u64 t; cvta.to.shared.u64 t, %1; cvt.u32.u64 %0, t; }"
        : "=r"(a) : "l"(p));
    return a;
}
#define CP_ASYNC16(dst, src) asm volatile("cp.async.cg.shared.global [%0], [%1], 16;" :: "r"(dst), "l"(src))
#define CP_COMMIT()          asm volatile("cp.async.commit_group;" ::: "memory")
#define CP_WAIT1()           asm volatile("cp.async.wait_group 1;" ::: "memory")
#define CP_WAIT0()           asm volatile("cp.async.wait_group 0;" ::: "memory")

__device__ __forceinline__ uint32_t sw128(uint32_t off) {
    return off ^ ((off >> 3) & 0x70);
}
__device__ __forceinline__ void ldsm4(uint32_t& r0, uint32_t& r1,
                                      uint32_t& r2, uint32_t& r3, uint32_t a) {
    asm volatile("ldmatrix.sync.aligned.m8n8.x4.shared.b16 {%0,%1,%2,%3}, [%4];"
                 : "=r"(r0), "=r"(r1), "=r"(r2), "=r"(r3) : "r"(a));
}
__device__ __forceinline__ void mma16816(float* c, const uint32_t* a,
                                         const uint32_t* b) {
    asm volatile("mma.sync.aligned.m16n8k16.row.col.f32.bf16.bf16.f32 "
        "{%0,%1,%2,%3}, {%4,%5,%6,%7}, {%8,%9}, {%0,%1,%2,%3};"
        : "+f"(c[0]), "+f"(c[1]), "+f"(c[2]), "+f"(c[3])
        : "r"(a[0]), "r"(a[1]), "r"(a[2]), "r"(a[3]), "r"(b[0]), "r"(b[1]));
}
__device__ __forceinline__ uint32_t pack_bf2(__nv_bfloat16 a, __nv_bfloat16 b) {
    return (uint32_t)__bfloat16_as_ushort(a)
         | ((uint32_t)__bfloat16_as_ushort(b) << 16);
}
__device__ __forceinline__ void bsplit(float v, __nv_bfloat16& h, __nv_bfloat16& l) {
    h = __float2bfloat16(v);
    l = __float2bfloat16(v - __bfloat162float(h));
}
__device__ __forceinline__ void split4(float4 v, uint2& H, uint2& L) {
    __nv_bfloat16 h0, h1, h2, h3, l0, l1, l2, l3;
    bsplit(v.x, h0, l0); bsplit(v.y, h1, l1);
    bsplit(v.z, h2, l2); bsplit(v.w, h3, l3);
    H.x = pack_bf2(h0, h1); H.y = pack_bf2(h2, h3);
    L.x = pack_bf2(l0, l1); L.y = pack_bf2(l2, l3);
}

// ---------------------------------------------------------------------------
// conversions: fp32 -> (hi, lo) bf16
// ---------------------------------------------------------------------------
__global__ __launch_bounds__(256) void conv_x_kernel(const float* __restrict__ x) {
    size_t i = (size_t)blockIdx.x * 256 + threadIdx.x;
    float4 v = ((const float4*)x)[i];
    uint2 H, L;
    split4(v, H, L);
    *(uint2*)&g_xh[4 * i] = H;
    *(uint2*)&g_xl[4 * i] = L;
}
__global__ __launch_bounds__(256) void conv_rw_kernel(const float* __restrict__ rw) {
    size_t i = (size_t)blockIdx.x * 256 + threadIdx.x;
    float4 v = ((const float4*)rw)[i];
    uint2 H, L;
    split4(v, H, L);
    *(uint2*)&g_rwh[4 * i] = H;
    *(uint2*)&g_rwl[4 * i] = L;
}

// ---------------------------------------------------------------------------
// feats via mma.sync: D[n,d] = sum_k x[n,k]*rw[d,k]  (3-term hi/lo bf16)
// CTA tile 128n x 128d, K=256 in 4 chunks of 64, double buffered cp.async.
// 8 warps as 2(m) x 4(n); warp tile 64 x 32. grid (2, 8, 32).
// ---------------------------------------------------------------------------
#define F_SMEM (1024 + 2 * 65536)
__global__ __launch_bounds__(256) void feats_mma_kernel(const float* __restrict__ rb) {
    extern __shared__ char smem[];
    const uint32_t ab = (smem_u32(smem) + 1023) & ~1023u;
    const int tid = threadIdx.x, wid = tid >> 5, lane = tid & 31;
    const int d0 = blockIdx.x * 128;
    const int n0 = blockIdx.y * 128;
    const int br = blockIdx.z, b = br >> 2, r = br & 3;
    const int wm = (wid >> 2) * 64, wn = (wid & 3) * 32;

    auto prefetch = [&](int c, int stage) {
        uint32_t base = ab + stage * 65536;
        for (int u = tid; u < 4096; u += 256) {
            int t = u >> 10, v = u & 1023, row = v >> 3, un = v & 7;
            uint32_t dst = base + t * 16384 + sw128(row * 128 + un * 16);
            const __nv_bfloat16* src;
            if (t < 2) {
                src = (t ? g_xl : g_xh)
                    + (size_t)b * (Nn * DIN) + (size_t)(n0 + row) * DIN + c * 64 + un * 8;
            } else {
                src = (t == 2 ? g_rwh : g_rwl)
                    + (size_t)r * (DOUT * DIN) + (size_t)(d0 + row) * DIN + c * 64 + un * 8;
            }
            CP_ASYNC16(dst, (const char*)src);
        }
        CP_COMMIT();
    };

    float acc[4][4][4] = {};
    const int grp = lane >> 3, l7 = lane & 7;
    const int arow = (grp & 1) * 8 + l7, ac16 = (grp >> 1) * 16;
    const int brow = (grp >> 1) * 8 + l7, bc16 = (grp & 1) * 16;

    prefetch(0, 0);
    for (int c = 0; c < 4; c++) {
        if (c + 1 < 4) { prefetch(c + 1, (c + 1) & 1); CP_WAIT1(); }
        else           { CP_WAIT0(); }
        __syncthreads();
        uint32_t base = ab + (c & 1) * 65536;
        #pragma unroll
        for (int ks = 0; ks < 4; ks++) {
            int kb = ks * 32;
            uint32_t Ah[4][4], Al[4][4], Bh[4][2], Bl[4][2];
            #pragma unroll
            for (int mf = 0; mf < 4; mf++) {
                uint32_t off = sw128((wm + mf * 16 + arow) * 128 + kb + ac16);
                ldsm4(Ah[mf][0], Ah[mf][1], Ah[mf][2], Ah[mf][3], base + off);
                ldsm4(Al[mf][0], Al[mf][1], Al[mf][2], Al[mf][3], base + 16384 + off);
            }
            #pragma unroll
            for (int g = 0; g < 2; g++) {
                uint32_t off = sw128((wn + g * 16 + brow) * 128 + kb + bc16);
                uint32_t t0, t1, t2, t3;
                ldsm4(t0, t1, t2, t3, base + 32768 + off);
                Bh[2*g][0] = t0; Bh[2*g][1] = t1; Bh[2*g+1][0] = t2; Bh[2*g+1][1] = t3;
                ldsm4(t0, t1, t2, t3, base + 49152 + off);
                Bl[2*g][0] = t0; Bl[2*g][1] = t1; Bl[2*g+1][0] = t2; Bl[2*g+1][1] = t3;
            }
            #pragma unroll
            for (int mf = 0; mf < 4; mf++)
                #pragma unroll
                for (int nf = 0; nf < 4; nf++) {
                    mma16816(acc[mf][nf], Ah[mf], Bh[nf]);
                    mma16816(acc[mf][nf], Ah[mf], Bl[nf]);
                    mma16816(acc[mf][nf], Al[mf], Bh[nf]);
                }
        }
        __syncthreads();
    }

    #pragma unroll
    for (int nf = 0; nf < 4; nf++) {
        int col = d0 + wn + nf * 8 + 2 * (lane & 3);
        float b0 = rb[r * DOUT + col], b1 = rb[r * DOUT + col + 1];
        #pragma unroll
        for (int mf = 0; mf < 4; mf++) {
            int row = n0 + wm + mf * 16 + (lane >> 2);
            float* p0 = g_feats + ((size_t)br * Nn + row) * DOUT + col;
            float* p1 = g_feats + ((size_t)br * Nn + row + 8) * DOUT + col;
            p0[0] = acc[mf][nf][0] + b0; p0[1] = acc[mf][nf][1] + b1;
            p1[0] = acc[mf][nf][2] + b0; p1[1] = acc[mf][nf][3] + b1;
        }
    }
}

// ---------------------------------------------------------------------------
// wf kernel v2: sj = feats . attn_w[256:], w = exp(sj); write wf^T hi/lo bf16
// block = 128 m-rows of one br; smem transpose -> coalesced 256B row writes.
// grid Bq*Rr*8 = 256 blocks, 256 threads.
// ---------------------------------------------------------------------------
#define TPAD 136
__global__ __launch_bounds__(256) void wf_kernel(const float* __restrict__ aw) {
    __shared__ float awj[256];
    __shared__ float ws[128];
    __shared__ __align__(16) __nv_bfloat16 th[64][TPAD];
    __shared__ __align__(16) __nv_bfloat16 tl[64][TPAD];
    const int tid = threadIdx.x, wid = tid >> 5, lane = tid & 31;
    const int br = blockIdx.x >> 3, mt = blockIdx.x & 7;
    const int m0 = mt * 128;

    awj[tid] = aw[DOUT + tid];
    __syncthreads();

    const float* F = g_feats + ((size_t)br * Nn + m0) * DOUT;

    // sj + w for 128 rows: each warp 16 rows
    #pragma unroll
    for (int i = 0; i < 16; i++) {
        int m = wid * 16 + i;
        float s = 0.f;
        #pragma unroll
        for (int k = 0; k < 8; k++)
            s = fmaf(F[(size_t)m * DOUT + lane + k * 32], awj[lane + k * 32], s);
        #pragma unroll
        for (int o = 16; o; o >>= 1) s += __shfl_xor_sync(0xffffffffu, s, o);
        if (lane == 0) {
            float w = __expf(s);
            ws[m] = w;
            g_w[br * Nn + m0 + m] = w;
        }
    }
    __syncthreads();

    // 4 d-chunks of 64: transpose-scale in smem, write coalesced
    for (int dc = 0; dc < 4; dc++) {
        #pragma unroll
        for (int it = 0; it < 8; it++) {
            int idx = it * 256 + tid;
            int m = idx >> 4, dq = idx & 15;
            float4 v = *(const float4*)&F[(size_t)m * DOUT + dc * 64 + dq * 4];
            float w = ws[m];
            __nv_bfloat16 h, l;
            bsplit(v.x * w, h, l); th[dq*4+0][m] = h; tl[dq*4+0][m] = l;
            bsplit(v.y * w, h, l); th[dq*4+1][m] = h; tl[dq*4+1][m] = l;
            bsplit(v.z * w, h, l); th[dq*4+2][m] = h; tl[dq*4+2][m] = l;
            bsplit(v.w * w, h, l); th[dq*4+3][m] = h; tl[dq*4+3][m] = l;
        }
        __syncthreads();
        #pragma unroll
        for (int it = 0; it < 4; it++) {
            int idx = it * 256 + tid;
            int d = idx >> 4, mq = idx & 15;
            size_t go = ((size_t)br * DOUT + dc * 64 + d) * Nn + m0 + mq * 8;
            *(uint4*)&g_wfh[go] = *(uint4*)&th[d][mq * 8];
            *(uint4*)&g_wfl[go] = *(uint4*)&tl[d][mq * 8];
        }
        __syncthreads();
    }
}

// ---------------------------------------------------------------------------
// prepass: adj int32 -> bf16 {0,1}; invZ[br,n] = 1 / sum_m adj[n,m]*w[m]
// ---------------------------------------------------------------------------
__global__ __launch_bounds__(256) void prepass_kernel(const int* __restrict__ adj) {
    __shared__ float ws[Nn];
    const int tid = threadIdx.x, wid = tid >> 5, lane = tid & 31;
    const int br = blockIdx.x >> 5, nb = blockIdx.x & 31;
    for (int i = tid; i < Nn; i += 256) ws[i] = g_w[br * Nn + i];
    __syncthreads();

    #pragma unroll
    for (int i = 0; i < 4; i++) {
        int n = nb * 32 + wid * 4 + i;
        const int4* arow = (const int4*)(adj + (((size_t)br << 10) + n) * Nn);
        __nv_bfloat16* brow = g_adjbf + (((size_t)br << 10) + n) * Nn;
        float z = 0.f;
        #pragma unroll
        for (int k = 0; k < 8; k++) {
            int m = k * 128 + lane * 4;
            int4 a = arow[k * 32 + lane];
            uint2 o;
            o.x = (a.x ? 0x3F80u : 0u) | ((a.y ? 0x3F80u : 0u) << 16);
            o.y = (a.z ? 0x3F80u : 0u) | ((a.w ? 0x3F80u : 0u) << 16);
            *(uint2*)(brow + m) = o;
            if (a.x) z += ws[m];
            if (a.y) z += ws[m + 1];
            if (a.z) z += ws[m + 2];
            if (a.w) z += ws[m + 3];
        }
        #pragma unroll
        for (int o = 16; o; o >>= 1) z += __shfl_xor_sync(0xffffffffu, z, o);
        if (lane == 0) g_invZ[(br << 10) + n] = 1.0f / z;
    }
}

// ---------------------------------------------------------------------------
// agg via mma.sync: out[b,n,d] = sum_r invZ[r,n] * (adj_r @ wf_r^T)[n,d]
// CTA tile 128n x 128d; 32 super-chunks of K=128 (2 sub-chunks of 64 each).
// 8 warps 2x4, warp tile 64x32. grid (2, 8, 8).
// super-stage: 2 x (A | Bh | Bl) 48KB = 96KB, double buffered (192KB).
// ---------------------------------------------------------------------------
#define A_SMEM (1024 + 2 * 98304)
__global__ __launch_bounds__(256) void agg_mma_kernel(float* __restrict__ out) {
    extern __shared__ char smem[];
    __shared__ float izs[Rr * 128];
    const uint32_t ab = (smem_u32(smem) + 1023) & ~1023u;
    const int tid = threadIdx.x, wid = tid >> 5, lane = tid & 31;
    const int d0 = blockIdx.x * 128;
    const int n0 = blockIdx.y * 128;
    const int b  = blockIdx.z;
    const int wm = (wid >> 2) * 64, wn = (wid & 3) * 32;

    for (int i = tid; i < Rr * 128; i += 256)
        izs[i] = g_invZ[((b * Rr + (i >> 7)) << 10) + n0 + (i & 127)];

    // super-chunk sc covers chunks 2*sc, 2*sc+1 (each 64 k)
    auto prefetch = [&](int sc, int stage) {
        uint32_t sbase = ab + stage * 98304;
        #pragma unroll
        for (int cc = 0; cc < 2; cc++) {
            int c = sc * 2 + cc;
            int r = c >> 4, kc = c & 15, m0 = kc * 64;
            uint32_t base = sbase + cc * 49152;
            size_t brr = (size_t)(b * Rr + r);
            for (int u = tid; u < 3072; u += 256) {
                int t = u >> 10, v = u & 1023, row = v >> 3, un = v & 7;
                uint32_t dst = base + t * 16384 + sw128(row * 128 + un * 16);
                const __nv_bfloat16* src;
                if (t == 0)      src = g_adjbf + (brr * Nn + n0 + row) * Nn + m0 + un * 8;
                else if (t == 1) src = g_wfh + (brr * DOUT + d0 + row) * Nn + m0 + un * 8;
                else             src = g_wfl + (brr * DOUT + d0 + row) * Nn + m0 + un * 8;
                CP_ASYNC16(dst, (const char*)src);
            }
        }
        CP_COMMIT();
    };

    float total[4][4][4] = {};
    float acc[4][4][4] = {};
    const int grp = lane >> 3, l7 = lane & 7;
    const int arow = (grp & 1) * 8 + l7, ac16 = (grp >> 1) * 16;
    const int brow = (grp >> 1) * 8 + l7, bc16 = (grp & 1) * 16;
    const int SC = 32;

    prefetch(0, 0);
    for (int sc = 0; sc < SC; sc++) {
        if (sc + 1 < SC) { prefetch(sc + 1, (sc + 1) & 1); CP_WAIT1(); }
        else             { CP_WAIT0(); }
        __syncthreads();
        uint32_t sbase = ab + (sc & 1) * 98304;
        #pragma unroll
        for (int cc = 0; cc < 2; cc++) {
            uint32_t base = sbase + cc * 49152;
            #pragma unroll
            for (int ks = 0; ks < 4; ks++) {
                int kb = ks * 32;
                uint32_t A[4][4], Bh[4][2], Bl[4][2];
                #pragma unroll
                for (int mf = 0; mf < 4; mf++) {
                    uint32_t off = sw128((wm + mf * 16 + arow) * 128 + kb + ac16);
                    ldsm4(A[mf][0], A[mf][1], A[mf][2], A[mf][3], base + off);
                }
                #pragma unroll
                for (int g = 0; g < 2; g++) {
                    uint32_t off = sw128((wn + g * 16 + brow) * 128 + kb + bc16);
                    uint32_t t0, t1, t2, t3;
                    ldsm4(t0, t1, t2, t3, base + 16384 + off);
                    Bh[2*g][0] = t0; Bh[2*g][1] = t1; Bh[2*g+1][0] = t2; Bh[2*g+1][1] = t3;
                    ldsm4(t0, t1, t2, t3, base + 32768 + off);
                    Bl[2*g][0] = t0; Bl[2*g][1] = t1; Bl[2*g+1][0] = t2; Bl[2*g+1][1] = t3;
                }
                #pragma unroll
                for (int mf = 0; mf < 4; mf++)
                    #pragma unroll
                    for (int nf = 0; nf < 4; nf++) {
                        mma16816(acc[mf][nf], A[mf], Bh[nf]);
                        mma16816(acc[mf][nf], A[mf], Bl[nf]);
                    }
            }
        }
        __syncthreads();

        if ((sc & 7) == 7) {             // end of relation r: fold with invZ
            int r = sc >> 3;
            #pragma unroll
            for (int mf = 0; mf < 4; mf++) {
                float iz0 = izs[r * 128 + wm + mf * 16 + (lane >> 2)];
                float iz1 = izs[r * 128 + wm + mf * 16 + (lane >> 2) + 8];
                #pragma unroll
                for (int nf = 0; nf < 4; nf++) {
                    total[mf][nf][0] = fmaf(iz0, acc[mf][nf][0], total[mf][nf][0]);
                    total[mf][nf][1] = fmaf(iz0, acc[mf][nf][1], total[mf][nf][1]);
                    total[mf][nf][2] = fmaf(iz1, acc[mf][nf][2], total[mf][nf][2]);
                    total[mf][nf][3] = fmaf(iz1, acc[mf][nf][3], total[mf][nf][3]);
                    acc[mf][nf][0] = 0.f; acc[mf][nf][1] = 0.f;
                    acc[mf][nf][2] = 0.f; acc[mf][nf][3] = 0.f;
                }
            }
        }
    }

    #pragma unroll
    for (int nf = 0; nf < 4; nf++) {
        int col = d0 + wn + nf * 8 + 2 * (lane & 3);
        #pragma unroll
        for (int mf = 0; mf < 4; mf++) {
            int row = n0 + wm + mf * 16 + (lane >> 2);
            float* p0 = out + ((size_t)b * Nn + row) * DOUT + col;
            float* p1 = out + ((size_t)b * Nn + row + 8) * DOUT + col;
            p0[0] = total[mf][nf][0]; p0[1] = total[mf][nf][1];
            p1[0] = total[mf][nf][2]; p1[1] = total[mf][nf][3];
        }
    }
}

// ---------------------------------------------------------------------------
// gate epilogue: out = sigmoid(out . gw + gb) * out, one block per (b,n)
// ---------------------------------------------------------------------------
__global__ __launch_bounds__(256) void gate_kernel(
    float* __restrict__ out, const float* __restrict__ gw,
    const float* __restrict__ gb_p)
{
    __shared__ float red[8];
    float* o = out + (size_t)blockIdx.x * DOUT;
    int t = threadIdx.x, lane = t & 31;
    float a = o[t];
    float v = a * gw[t];
    #pragma unroll
    for (int off = 16; off; off >>= 1) v += __shfl_xor_sync(0xffffffffu, v, off);
    if (lane == 0) red[t >> 5] = v;
    __syncthreads();
    if (t < 32) {
        float r = (t < 8) ? red[t] : 0.0f;
        #pragma unroll
        for (int off = 4; off; off >>= 1) r += __shfl_xor_sync(0xffffffffu, r, off);
        if (t == 0) red[0] = r;
    }
    __syncthreads();
    float g = 1.0f / (1.0f + __expf(-(red[0] + gb_p[0])));
    o[t] = g * a;
}

// ---------------------------------------------------------------------------
extern "C" void kernel_launch(void* const* d_in, const int* in_sizes, int n_in,
                              void* d_out, int out_size)
{
    const float* x   = (const float*)d_in[0];
    const int*   adj = (const int*)  d_in[1];
    const float* rw  = (const float*)d_in[2];
    const float* rb  = (const float*)d_in[3];
    const float* aw  = (const float*)d_in[4];
    const float* gw  = (const float*)d_in[6];
    const float* gb  = (const float*)d_in[7];
    float* out = (float*)d_out;

    cudaFuncSetAttribute(feats_mma_kernel,
                         cudaFuncAttributeMaxDynamicSharedMemorySize, F_SMEM);
    cudaFuncSetAttribute(agg_mma_kernel,
                         cudaFuncAttributeMaxDynamicSharedMemorySize, A_SMEM);

    conv_x_kernel<<<(Bq * Nn * DIN / 4) / 256, 256>>>(x);
    conv_rw_kernel<<<(Rr * DOUT * DIN / 4) / 256, 256>>>(rw);

    feats_mma_kernel<<<dim3(2, 8, Bq * Rr), 256, F_SMEM>>>(rb);

    wf_kernel<<<Bq * Rr * 8, 256>>>(aw);

    prepass_kernel<<<Bq * Rr * 32, 256>>>(adj);

    agg_mma_kernel<<<dim3(2, 8, Bq), 256, A_SMEM>>>(out);

    gate_kernel<<<Bq * Nn, 256>>>(out, gw, gb);
}

// round 6
// speedup vs baseline: 1.1575x; 1.1575x over previous
#include <cuda_runtime.h>
#include <cuda_bf16.h>
#include <cstdint>

#define Bq   8
#define Nn   1024
#define DIN  256
#define DOUT 256
#define Rr   4

// ------------------------- scratch globals ----------------------------------
__device__ __nv_bfloat16 g_xh[(size_t)Bq * Nn * DIN];
__device__ __nv_bfloat16 g_xl[(size_t)Bq * Nn * DIN];
__device__ __nv_bfloat16 g_rwh[(size_t)Rr * DOUT * DIN];
__device__ __nv_bfloat16 g_rwl[(size_t)Rr * DOUT * DIN];
__device__ float         g_w[Bq * Rr * Nn];
__device__ float         g_invZ[Bq * Rr * Nn];
__device__ __nv_bfloat16 g_wfh[(size_t)Bq * Rr * DOUT * Nn];     // wf^T hi [br][d][m]
__device__ __nv_bfloat16 g_wfl[(size_t)Bq * Rr * DOUT * Nn];     // wf^T lo
__device__ __nv_bfloat16 g_adjbf[(size_t)Bq * Rr * Nn * Nn];     // 64 MB

// ------------------------- helpers ------------------------------------------
__device__ __forceinline__ uint32_t smem_u32(const void* p) {
    uint32_t a;
    asm("{ .reg .u64 t; cvta.to.shared.u64 t, %1; cvt.u32.u64 %0, t; }"
        : "=r"(a) : "l"(p));
    return a;
}
#define CP_ASYNC16(dst, src) asm volatile("cp.async.cg.shared.global [%0], [%1], 16;" :: "r"(dst), "l"(src))
#define CP_COMMIT()          asm volatile("cp.async.commit_group;" ::: "memory")
#define CP_WAIT1()           asm volatile("cp.async.wait_group 1;" ::: "memory")
#define CP_WAIT0()           asm volatile("cp.async.wait_group 0;" ::: "memory")

__device__ __forceinline__ uint32_t sw128(uint32_t off) {
    return off ^ ((off >> 3) & 0x70);
}
__device__ __forceinline__ void ldsm4(uint32_t& r0, uint32_t& r1,
                                      uint32_t& r2, uint32_t& r3, uint32_t a) {
    asm volatile("ldmatrix.sync.aligned.m8n8.x4.shared.b16 {%0,%1,%2,%3}, [%4];"
                 : "=r"(r0), "=r"(r1), "=r"(r2), "=r"(r3) : "r"(a));
}
__device__ __forceinline__ void mma16816(float* c, const uint32_t* a,
                                         const uint32_t* b) {
    asm volatile("mma.sync.aligned.m16n8k16.row.col.f32.bf16.bf16.f32 "
        "{%0,%1,%2,%3}, {%4,%5,%6,%7}, {%8,%9}, {%0,%1,%2,%3};"
        : "+f"(c[0]), "+f"(c[1]), "+f"(c[2]), "+f"(c[3])
        : "r"(a[0]), "r"(a[1]), "r"(a[2]), "r"(a[3]), "r"(b[0]), "r"(b[1]));
}
__device__ __forceinline__ uint32_t pack_bf2(__nv_bfloat16 a, __nv_bfloat16 b) {
    return (uint32_t)__bfloat16_as_ushort(a)
         | ((uint32_t)__bfloat16_as_ushort(b) << 16);
}
__device__ __forceinline__ void bsplit(float v, __nv_bfloat16& h, __nv_bfloat16& l) {
    h = __float2bfloat16(v);
    l = __float2bfloat16(v - __bfloat162float(h));
}
__device__ __forceinline__ void split4(float4 v, uint2& H, uint2& L) {
    __nv_bfloat16 h0, h1, h2, h3, l0, l1, l2, l3;
    bsplit(v.x, h0, l0); bsplit(v.y, h1, l1);
    bsplit(v.z, h2, l2); bsplit(v.w, h3, l3);
    H.x = pack_bf2(h0, h1); H.y = pack_bf2(h2, h3);
    L.x = pack_bf2(l0, l1); L.y = pack_bf2(l2, l3);
}

// ---------------------------------------------------------------------------
// conversions: fp32 -> (hi, lo) bf16
// ---------------------------------------------------------------------------
__global__ __launch_bounds__(256) void conv_x_kernel(const float* __restrict__ x) {
    size_t i = (size_t)blockIdx.x * 256 + threadIdx.x;
    float4 v = ((const float4*)x)[i];
    uint2 H, L;
    split4(v, H, L);
    *(uint2*)&g_xh[4 * i] = H;
    *(uint2*)&g_xl[4 * i] = L;
}
__global__ __launch_bounds__(256) void conv_rw_kernel(const float* __restrict__ rw) {
    size_t i = (size_t)blockIdx.x * 256 + threadIdx.x;
    float4 v = ((const float4*)rw)[i];
    uint2 H, L;
    split4(v, H, L);
    *(uint2*)&g_rwh[4 * i] = H;
    *(uint2*)&g_rwl[4 * i] = L;
}

// ---------------------------------------------------------------------------
// FUSED feats+wf kernel:
//   feats[n,d] = sum_k x[n,k]*rw[d,k] + rb[d]      (3-term hi/lo bf16 mma)
//   sj[n] = feats[n,:] . attn_w[256:]; w = exp(sj)
//   wf^T[d,m] = hi/lo bf16 of (w[m] * feats[m,d]), coalesced writes
// CTA: 128n x 256d (full d), K=256 in 4 chunks of 64, double buffered.
// 512 threads = 16 warps (4m x 4n), warp tile 32n x 64d.
// stage: Ah|Al (16KB ea) + Bh|Bl (32KB ea) = 96KB, x2 = 192KB dynamic.
// epilogue reuses stage smem as 2 x 64KB bf16 transpose buffers.
// grid (8 n-tiles, 32 br).
// ---------------------------------------------------------------------------
#define FW_SMEM (1024 + 2 * 98304)
__global__ __launch_bounds__(512, 1) void fw_kernel(
    const float* __restrict__ rb, const float* __restrict__ aw)
{
    extern __shared__ char smem[];
    __shared__ float awjs[256];
    __shared__ float rbs[256];
    __shared__ float sjred[4][128];
    __shared__ float wsm[128];
    char* abp = (char*)(((uintptr_t)smem + 1023) & ~(uintptr_t)1023);
    const uint32_t ab = (smem_u32(smem) + 1023) & ~1023u;
    const int tid = threadIdx.x, wid = tid >> 5, lane = tid & 31;
    const int n0 = blockIdx.x * 128;
    const int br = blockIdx.y, b = br >> 2, r = br & 3;
    const int wm = (wid >> 2) * 32, wn = (wid & 3) * 64;

    if (tid < 256) { awjs[tid] = aw[DOUT + tid]; rbs[tid] = rb[r * DOUT + tid]; }

    auto prefetch = [&](int c, int stage) {
        uint32_t base = ab + stage * 98304;
        for (int u = tid; u < 6144; u += 512) {
            uint32_t dst;
            const __nv_bfloat16* src;
            if (u < 2048) {           // Ah | Al: 128 rows x 64 k
                int t = u >> 10, v = u & 1023, row = v >> 3, un = v & 7;
                dst = base + t * 16384 + sw128(row * 128 + un * 16);
                src = (t ? g_xl : g_xh)
                    + (size_t)b * (Nn * DIN) + (size_t)(n0 + row) * DIN + c * 64 + un * 8;
            } else {                  // Bh | Bl: 256 rows x 64 k
                int v2 = u - 2048;
                int t = v2 >> 11, v = v2 & 2047, row = v >> 3, un = v & 7;
                dst = base + 32768 + t * 32768 + sw128(row * 128 + un * 16);
                src = (t ? g_rwl : g_rwh)
                    + (size_t)r * (DOUT * DIN) + (size_t)row * DIN + c * 64 + un * 8;
            }
            CP_ASYNC16(dst, (const char*)src);
        }
        CP_COMMIT();
    };

    float acc[2][8][4] = {};
    const int grp = lane >> 3, l7 = lane & 7;
    const int arow = (grp & 1) * 8 + l7, ac16 = (grp >> 1) * 16;
    const int brow = (grp >> 1) * 8 + l7, bc16 = (grp & 1) * 16;

    prefetch(0, 0);
    for (int c = 0; c < 4; c++) {
        if (c + 1 < 4) { prefetch(c + 1, (c + 1) & 1); CP_WAIT1(); }
        else           { CP_WAIT0(); }
        __syncthreads();
        uint32_t base = ab + (c & 1) * 98304;
        #pragma unroll
        for (int ks = 0; ks < 4; ks++) {
            int kb = ks * 32;
            uint32_t Ah[2][4], Al[2][4];
            #pragma unroll
            for (int mf = 0; mf < 2; mf++) {
                uint32_t off = sw128((wm + mf * 16 + arow) * 128 + kb + ac16);
                ldsm4(Ah[mf][0], Ah[mf][1], Ah[mf][2], Ah[mf][3], base + off);
                ldsm4(Al[mf][0], Al[mf][1], Al[mf][2], Al[mf][3], base + 16384 + off);
            }
            #pragma unroll
            for (int g = 0; g < 4; g++) {
                uint32_t off = sw128((wn + g * 16 + brow) * 128 + kb + bc16);
                uint32_t h0, h1, h2, h3, q0, q1, q2, q3;
                ldsm4(h0, h1, h2, h3, base + 32768 + off);
                ldsm4(q0, q1, q2, q3, base + 65536 + off);
                uint32_t Bh0[2] = {h0, h1}, Bh1[2] = {h2, h3};
                uint32_t Bl0[2] = {q0, q1}, Bl1[2] = {q2, q3};
                #pragma unroll
                for (int mf = 0; mf < 2; mf++) {
                    mma16816(acc[mf][2*g],   Ah[mf], Bh0);
                    mma16816(acc[mf][2*g+1], Ah[mf], Bh1);
                    mma16816(acc[mf][2*g],   Al[mf], Bh0);
                    mma16816(acc[mf][2*g+1], Al[mf], Bh1);
                    mma16816(acc[mf][2*g],   Ah[mf], Bl0);
                    mma16816(acc[mf][2*g+1], Ah[mf], Bl1);
                }
            }
        }
        __syncthreads();
    }

    // ---- epilogue: bias, sj reduction, w, scale, transpose, store ----------
    #pragma unroll
    for (int nf = 0; nf < 8; nf++) {
        int c0 = wn + nf * 8 + 2 * (lane & 3);
        float b0 = rbs[c0], b1 = rbs[c0 + 1];
        #pragma unroll
        for (int mf = 0; mf < 2; mf++) {
            acc[mf][nf][0] += b0; acc[mf][nf][1] += b1;
            acc[mf][nf][2] += b0; acc[mf][nf][3] += b1;
        }
    }

    // sj partials over this warp's 64 cols
    float p[2][2] = {};
    #pragma unroll
    for (int nf = 0; nf < 8; nf++) {
        int c0 = wn + nf * 8 + 2 * (lane & 3);
        float a0 = awjs[c0], a1 = awjs[c0 + 1];
        #pragma unroll
        for (int mf = 0; mf < 2; mf++) {
            p[mf][0] = fmaf(acc[mf][nf][0], a0, fmaf(acc[mf][nf][1], a1, p[mf][0]));
            p[mf][1] = fmaf(acc[mf][nf][2], a0, fmaf(acc[mf][nf][3], a1, p[mf][1]));
        }
    }
    #pragma unroll
    for (int mf = 0; mf < 2; mf++)
        #pragma unroll
        for (int q = 0; q < 2; q++) {
            p[mf][q] += __shfl_xor_sync(0xffffffffu, p[mf][q], 1);
            p[mf][q] += __shfl_xor_sync(0xffffffffu, p[mf][q], 2);
            if ((lane & 3) == 0)
                sjred[wid & 3][wm + mf * 16 + q * 8 + (lane >> 2)] = p[mf][q];
        }
    __syncthreads();

    if (tid < 128) {
        float s = sjred[0][tid] + sjred[1][tid] + sjred[2][tid] + sjred[3][tid];
        float w = __expf(s);
        wsm[tid] = w;
        g_w[br * Nn + n0 + tid] = w;
    }
    __syncthreads();

    // scale + hi/lo split into transpose smem (reuse stage area):
    // thi[d][m] at abp, tlo at abp + 65536 (each 256 x 128 bf16 = 64KB)
    __nv_bfloat16* thi = (__nv_bfloat16*)abp;
    __nv_bfloat16* tlo = (__nv_bfloat16*)(abp + 65536);
    #pragma unroll
    for (int mf = 0; mf < 2; mf++)
        #pragma unroll
        for (int q = 0; q < 2; q++) {
            int row = wm + mf * 16 + q * 8 + (lane >> 2);
            float w = wsm[row];
            #pragma unroll
            for (int nf = 0; nf < 8; nf++) {
                int c0 = wn + nf * 8 + 2 * (lane & 3);
                __nv_bfloat16 h, l;
                bsplit(acc[mf][nf][2 * q] * w, h, l);
                thi[c0 * 128 + row] = h; tlo[c0 * 128 + row] = l;
                bsplit(acc[mf][nf][2 * q + 1] * w, h, l);
                thi[(c0 + 1) * 128 + row] = h; tlo[(c0 + 1) * 128 + row] = l;
            }
        }
    __syncthreads();

    // coalesced writes: 256 d-rows x 128 m bf16 per array
    for (int it = 0; it < 8; it++) {
        int idx = it * 512 + tid;          // 0..4095
        int d = idx >> 4, mq = idx & 15;
        size_t go = ((size_t)br * DOUT + d) * Nn + n0 + mq * 8;
        *(uint4*)&g_wfh[go] = *(uint4*)&thi[d * 128 + mq * 8];
        *(uint4*)&g_wfl[go] = *(uint4*)&tlo[d * 128 + mq * 8];
    }
}

// ---------------------------------------------------------------------------
// prepass: adj int32 -> bf16 {0,1}; invZ[br,n] = 1 / sum_m adj[n,m]*w[m]
// ---------------------------------------------------------------------------
__global__ __launch_bounds__(256) void prepass_kernel(const int* __restrict__ adj) {
    __shared__ float ws[Nn];
    const int tid = threadIdx.x, wid = tid >> 5, lane = tid & 31;
    const int br = blockIdx.x >> 5, nb = blockIdx.x & 31;
    for (int i = tid; i < Nn; i += 256) ws[i] = g_w[br * Nn + i];
    __syncthreads();

    #pragma unroll
    for (int i = 0; i < 4; i++) {
        int n = nb * 32 + wid * 4 + i;
        const int4* arow = (const int4*)(adj + (((size_t)br << 10) + n) * Nn);
        __nv_bfloat16* brow = g_adjbf + (((size_t)br << 10) + n) * Nn;
        float z = 0.f;
        #pragma unroll
        for (int k = 0; k < 8; k++) {
            int m = k * 128 + lane * 4;
            int4 a = arow[k * 32 + lane];
            uint2 o;
            o.x = (a.x ? 0x3F80u : 0u) | ((a.y ? 0x3F80u : 0u) << 16);
            o.y = (a.z ? 0x3F80u : 0u) | ((a.w ? 0x3F80u : 0u) << 16);
            *(uint2*)(brow + m) = o;
            if (a.x) z += ws[m];
            if (a.y) z += ws[m + 1];
            if (a.z) z += ws[m + 2];
            if (a.w) z += ws[m + 3];
        }
        #pragma unroll
        for (int o = 16; o; o >>= 1) z += __shfl_xor_sync(0xffffffffu, z, o);
        if (lane == 0) g_invZ[(br << 10) + n] = 1.0f / z;
    }
}

// ---------------------------------------------------------------------------
// agg via mma.sync: out[b,n,d] = sum_r invZ[r,n] * (adj_r @ wf_r^T)[n,d]
// CTA tile 128n x 128d; 32 super-chunks of K=128 (2 sub-chunks of 64 each).
// 8 warps 2x4, warp tile 64x32. grid (2, 8, 8).
// ---------------------------------------------------------------------------
#define A_SMEM (1024 + 2 * 98304)
__global__ __launch_bounds__(256) void agg_mma_kernel(float* __restrict__ out) {
    extern __shared__ char smem[];
    __shared__ float izs[Rr * 128];
    const uint32_t ab = (smem_u32(smem) + 1023) & ~1023u;
    const int tid = threadIdx.x, wid = tid >> 5, lane = tid & 31;
    const int d0 = blockIdx.x * 128;
    const int n0 = blockIdx.y * 128;
    const int b  = blockIdx.z;
    const int wm = (wid >> 2) * 64, wn = (wid & 3) * 32;

    for (int i = tid; i < Rr * 128; i += 256)
        izs[i] = g_invZ[((b * Rr + (i >> 7)) << 10) + n0 + (i & 127)];

    auto prefetch = [&](int sc, int stage) {
        uint32_t sbase = ab + stage * 98304;
        #pragma unroll
        for (int cc = 0; cc < 2; cc++) {
            int c = sc * 2 + cc;
            int r = c >> 4, kc = c & 15, m0 = kc * 64;
            uint32_t base = sbase + cc * 49152;
            size_t brr = (size_t)(b * Rr + r);
            for (int u = tid; u < 3072; u += 256) {
                int t = u >> 10, v = u & 1023, row = v >> 3, un = v & 7;
                uint32_t dst = base + t * 16384 + sw128(row * 128 + un * 16);
                const __nv_bfloat16* src;
                if (t == 0)      src = g_adjbf + (brr * Nn + n0 + row) * Nn + m0 + un * 8;
                else if (t == 1) src = g_wfh + (brr * DOUT + d0 + row) * Nn + m0 + un * 8;
                else             src = g_wfl + (brr * DOUT + d0 + row) * Nn + m0 + un * 8;
                CP_ASYNC16(dst, (const char*)src);
            }
        }
        CP_COMMIT();
    };

    float total[4][4][4] = {};
    float acc[4][4][4] = {};
    const int grp = lane >> 3, l7 = lane & 7;
    const int arow = (grp & 1) * 8 + l7, ac16 = (grp >> 1) * 16;
    const int brow = (grp >> 1) * 8 + l7, bc16 = (grp & 1) * 16;
    const int SC = 32;

    prefetch(0, 0);
    for (int sc = 0; sc < SC; sc++) {
        if (sc + 1 < SC) { prefetch(sc + 1, (sc + 1) & 1); CP_WAIT1(); }
        else             { CP_WAIT0(); }
        __syncthreads();
        uint32_t sbase = ab + (sc & 1) * 98304;
        #pragma unroll
        for (int cc = 0; cc < 2; cc++) {
            uint32_t base = sbase + cc * 49152;
            #pragma unroll
            for (int ks = 0; ks < 4; ks++) {
                int kb = ks * 32;
                uint32_t A[4][4], Bh[4][2], Bl[4][2];
                #pragma unroll
                for (int mf = 0; mf < 4; mf++) {
                    uint32_t off = sw128((wm + mf * 16 + arow) * 128 + kb + ac16);
                    ldsm4(A[mf][0], A[mf][1], A[mf][2], A[mf][3], base + off);
                }
                #pragma unroll
                for (int g = 0; g < 2; g++) {
                    uint32_t off = sw128((wn + g * 16 + brow) * 128 + kb + bc16);
                    uint32_t t0, t1, t2, t3;
                    ldsm4(t0, t1, t2, t3, base + 16384 + off);
                    Bh[2*g][0] = t0; Bh[2*g][1] = t1; Bh[2*g+1][0] = t2; Bh[2*g+1][1] = t3;
                    ldsm4(t0, t1, t2, t3, base + 32768 + off);
                    Bl[2*g][0] = t0; Bl[2*g][1] = t1; Bl[2*g+1][0] = t2; Bl[2*g+1][1] = t3;
                }
                #pragma unroll
                for (int mf = 0; mf < 4; mf++)
                    #pragma unroll
                    for (int nf = 0; nf < 4; nf++) {
                        mma16816(acc[mf][nf], A[mf], Bh[nf]);
                        mma16816(acc[mf][nf], A[mf], Bl[nf]);
                    }
            }
        }
        __syncthreads();

        if ((sc & 7) == 7) {             // end of relation r: fold with invZ
            int r = sc >> 3;
            #pragma unroll
            for (int mf = 0; mf < 4; mf++) {
                float iz0 = izs[r * 128 + wm + mf * 16 + (lane >> 2)];
                float iz1 = izs[r * 128 + wm + mf * 16 + (lane >> 2) + 8];
                #pragma unroll
                for (int nf = 0; nf < 4; nf++) {
                    total[mf][nf][0] = fmaf(iz0, acc[mf][nf][0], total[mf][nf][0]);
                    total[mf][nf][1] = fmaf(iz0, acc[mf][nf][1], total[mf][nf][1]);
                    total[mf][nf][2] = fmaf(iz1, acc[mf][nf][2], total[mf][nf][2]);
                    total[mf][nf][3] = fmaf(iz1, acc[mf][nf][3], total[mf][nf][3]);
                    acc[mf][nf][0] = 0.f; acc[mf][nf][1] = 0.f;
                    acc[mf][nf][2] = 0.f; acc[mf][nf][3] = 0.f;
                }
            }
        }
    }

    #pragma unroll
    for (int nf = 0; nf < 4; nf++) {
        int col = d0 + wn + nf * 8 + 2 * (lane & 3);
        #pragma unroll
        for (int mf = 0; mf < 4; mf++) {
            int row = n0 + wm + mf * 16 + (lane >> 2);
            float* p0 = out + ((size_t)b * Nn + row) * DOUT + col;
            float* p1 = out + ((size_t)b * Nn + row + 8) * DOUT + col;
            p0[0] = total[mf][nf][0]; p0[1] = total[mf][nf][1];
            p1[0] = total[mf][nf][2]; p1[1] = total[mf][nf][3];
        }
    }
}

// ---------------------------------------------------------------------------
// gate epilogue: out = sigmoid(out . gw + gb) * out, one block per (b,n)
// ---------------------------------------------------------------------------
__global__ __launch_bounds__(256) void gate_kernel(
    float* __restrict__ out, const float* __restrict__ gw,
    const float* __restrict__ gb_p)
{
    __shared__ float red[8];
    float* o = out + (size_t)blockIdx.x * DOUT;
    int t = threadIdx.x, lane = t & 31;
    float a = o[t];
    float v = a * gw[t];
    #pragma unroll
    for (int off = 16; off; off >>= 1) v += __shfl_xor_sync(0xffffffffu, v, off);
    if (lane == 0) red[t >> 5] = v;
    __syncthreads();
    if (t < 32) {
        float r = (t < 8) ? red[t] : 0.0f;
        #pragma unroll
        for (int off = 4; off; off >>= 1) r += __shfl_xor_sync(0xffffffffu, r, off);
        if (t == 0) red[0] = r;
    }
    __syncthreads();
    float g = 1.0f / (1.0f + __expf(-(red[0] + gb_p[0])));
    o[t] = g * a;
}

// ---------------------------------------------------------------------------
extern "C" void kernel_launch(void* const* d_in, const int* in_sizes, int n_in,
                              void* d_out, int out_size)
{
    const float* x   = (const float*)d_in[0];
    const int*   adj = (const int*)  d_in[1];
    const float* rw  = (const float*)d_in[2];
    const float* rb  = (const float*)d_in[3];
    const float* aw  = (const float*)d_in[4];
    const float* gw  = (const float*)d_in[6];
    const float* gb  = (const float*)d_in[7];
    float* out = (float*)d_out;

    cudaFuncSetAttribute(fw_kernel,
                         cudaFuncAttributeMaxDynamicSharedMemorySize, FW_SMEM);
    cudaFuncSetAttribute(agg_mma_kernel,
                         cudaFuncAttributeMaxDynamicSharedMemorySize, A_SMEM);

    conv_x_kernel<<<(Bq * Nn * DIN / 4) / 256, 256>>>(x);
    conv_rw_kernel<<<(Rr * DOUT * DIN / 4) / 256, 256>>>(rw);

    fw_kernel<<<dim3(8, Bq * Rr), 512, FW_SMEM>>>(rb, aw);

    prepass_kernel<<<Bq * Rr * 32, 256>>>(adj);

    agg_mma_kernel<<<dim3(2, 8, Bq), 256, A_SMEM>>>(out);

    gate_kernel<<<Bq * Nn, 256>>>(out, gw, gb);
}

// round 7
// speedup vs baseline: 1.5642x; 1.3513x over previous
#include <cuda_runtime.h>
#include <cuda_bf16.h>
#include <cuda_fp16.h>
#include <cstdint>

#define Bq   8
#define Nn   1024
#define DIN  256
#define DOUT 256
#define Rr   4

// ------------------------- scratch globals ----------------------------------
__device__ __nv_bfloat16 g_xh[(size_t)Bq * Nn * DIN];
__device__ __nv_bfloat16 g_xl[(size_t)Bq * Nn * DIN];
__device__ __nv_bfloat16 g_rwh[(size_t)Rr * DOUT * DIN];
__device__ __nv_bfloat16 g_rwl[(size_t)Rr * DOUT * DIN];
__device__ float         g_w[Bq * Rr * Nn];
__device__ float         g_invZ[Bq * Rr * Nn];
__device__ __half        g_wff[(size_t)Bq * Rr * DOUT * Nn];     // wf^T fp16 [br][d][m]
__device__ __half        g_adjh[(size_t)Bq * Rr * Nn * Nn];      // 64 MB fp16 {0,1}

// ------------------------- helpers ------------------------------------------
__device__ __forceinline__ uint32_t smem_u32(const void* p) {
    uint32_t a;
    asm("{ .reg .u64 t; cvta.to.shared.u64 t, %1; cvt.u32.u64 %0, t; }"
        : "=r"(a) : "l"(p));
    return a;
}
#define CP_ASYNC16(dst, src) asm volatile("cp.async.cg.shared.global [%0], [%1], 16;" :: "r"(dst), "l"(src))
#define CP_COMMIT()          asm volatile("cp.async.commit_group;" ::: "memory")
#define CP_WAIT1()           asm volatile("cp.async.wait_group 1;" ::: "memory")
#define CP_WAIT0()           asm volatile("cp.async.wait_group 0;" ::: "memory")

__device__ __forceinline__ uint32_t sw128(uint32_t off) {
    return off ^ ((off >> 3) & 0x70);
}
__device__ __forceinline__ void ldsm4(uint32_t& r0, uint32_t& r1,
                                      uint32_t& r2, uint32_t& r3, uint32_t a) {
    asm volatile("ldmatrix.sync.aligned.m8n8.x4.shared.b16 {%0,%1,%2,%3}, [%4];"
                 : "=r"(r0), "=r"(r1), "=r"(r2), "=r"(r3) : "r"(a));
}
__device__ __forceinline__ void mma16816(float* c, const uint32_t* a,
                                         const uint32_t* b) {
    asm volatile("mma.sync.aligned.m16n8k16.row.col.f32.bf16.bf16.f32 "
        "{%0,%1,%2,%3}, {%4,%5,%6,%7}, {%8,%9}, {%0,%1,%2,%3};"
        : "+f"(c[0]), "+f"(c[1]), "+f"(c[2]), "+f"(c[3])
        : "r"(a[0]), "r"(a[1]), "r"(a[2]), "r"(a[3]), "r"(b[0]), "r"(b[1]));
}
__device__ __forceinline__ void mma16816h(float* c, const uint32_t* a,
                                          const uint32_t* b) {
    asm volatile("mma.sync.aligned.m16n8k16.row.col.f32.f16.f16.f32 "
        "{%0,%1,%2,%3}, {%4,%5,%6,%7}, {%8,%9}, {%0,%1,%2,%3};"
        : "+f"(c[0]), "+f"(c[1]), "+f"(c[2]), "+f"(c[3])
        : "r"(a[0]), "r"(a[1]), "r"(a[2]), "r"(a[3]), "r"(b[0]), "r"(b[1]));
}
__device__ __forceinline__ uint32_t pack_bf2(__nv_bfloat16 a, __nv_bfloat16 b) {
    return (uint32_t)__bfloat16_as_ushort(a)
         | ((uint32_t)__bfloat16_as_ushort(b) << 16);
}
__device__ __forceinline__ void bsplit(float v, __nv_bfloat16& h, __nv_bfloat16& l) {
    h = __float2bfloat16(v);
    l = __float2bfloat16(v - __bfloat162float(h));
}
__device__ __forceinline__ void split4(float4 v, uint2& H, uint2& L) {
    __nv_bfloat16 h0, h1, h2, h3, l0, l1, l2, l3;
    bsplit(v.x, h0, l0); bsplit(v.y, h1, l1);
    bsplit(v.z, h2, l2); bsplit(v.w, h3, l3);
    H.x = pack_bf2(h0, h1); H.y = pack_bf2(h2, h3);
    L.x = pack_bf2(l0, l1); L.y = pack_bf2(l2, l3);
}

// ---------------------------------------------------------------------------
// conversions: fp32 -> (hi, lo) bf16
// ---------------------------------------------------------------------------
__global__ __launch_bounds__(256) void conv_x_kernel(const float* __restrict__ x) {
    size_t i = (size_t)blockIdx.x * 256 + threadIdx.x;
    float4 v = ((const float4*)x)[i];
    uint2 H, L;
    split4(v, H, L);
    *(uint2*)&g_xh[4 * i] = H;
    *(uint2*)&g_xl[4 * i] = L;
}
__global__ __launch_bounds__(256) void conv_rw_kernel(const float* __restrict__ rw) {
    size_t i = (size_t)blockIdx.x * 256 + threadIdx.x;
    float4 v = ((const float4*)rw)[i];
    uint2 H, L;
    split4(v, H, L);
    *(uint2*)&g_rwh[4 * i] = H;
    *(uint2*)&g_rwl[4 * i] = L;
}

// ---------------------------------------------------------------------------
// FUSED feats+wf kernel (same MMA body as R6; epilogue writes single fp16):
//   feats[n,d] = sum_k x[n,k]*rw[d,k] + rb[d]      (3-term hi/lo bf16 mma)
//   sj[n] = feats[n,:] . attn_w[256:]; w = exp(sj)
//   wf^T[d,m] = fp16(w[m] * feats[m,d]), coalesced writes
// ---------------------------------------------------------------------------
#define FW_SMEM (1024 + 2 * 98304)
__global__ __launch_bounds__(512, 1) void fw_kernel(
    const float* __restrict__ rb, const float* __restrict__ aw)
{
    extern __shared__ char smem[];
    __shared__ float awjs[256];
    __shared__ float rbs[256];
    __shared__ float sjred[4][128];
    __shared__ float wsm[128];
    char* abp = (char*)(((uintptr_t)smem + 1023) & ~(uintptr_t)1023);
    const uint32_t ab = (smem_u32(smem) + 1023) & ~1023u;
    const int tid = threadIdx.x, wid = tid >> 5, lane = tid & 31;
    const int n0 = blockIdx.x * 128;
    const int br = blockIdx.y, b = br >> 2, r = br & 3;
    const int wm = (wid >> 2) * 32, wn = (wid & 3) * 64;

    if (tid < 256) { awjs[tid] = aw[DOUT + tid]; rbs[tid] = rb[r * DOUT + tid]; }

    auto prefetch = [&](int c, int stage) {
        uint32_t base = ab + stage * 98304;
        for (int u = tid; u < 6144; u += 512) {
            uint32_t dst;
            const __nv_bfloat16* src;
            if (u < 2048) {           // Ah | Al: 128 rows x 64 k
                int t = u >> 10, v = u & 1023, row = v >> 3, un = v & 7;
                dst = base + t * 16384 + sw128(row * 128 + un * 16);
                src = (t ? g_xl : g_xh)
                    + (size_t)b * (Nn * DIN) + (size_t)(n0 + row) * DIN + c * 64 + un * 8;
            } else {                  // Bh | Bl: 256 rows x 64 k
                int v2 = u - 2048;
                int t = v2 >> 11, v = v2 & 2047, row = v >> 3, un = v & 7;
                dst = base + 32768 + t * 32768 + sw128(row * 128 + un * 16);
                src = (t ? g_rwl : g_rwh)
                    + (size_t)r * (DOUT * DIN) + (size_t)row * DIN + c * 64 + un * 8;
            }
            CP_ASYNC16(dst, (const char*)src);
        }
        CP_COMMIT();
    };

    float acc[2][8][4] = {};
    const int grp = lane >> 3, l7 = lane & 7;
    const int arow = (grp & 1) * 8 + l7, ac16 = (grp >> 1) * 16;
    const int brow = (grp >> 1) * 8 + l7, bc16 = (grp & 1) * 16;

    prefetch(0, 0);
    for (int c = 0; c < 4; c++) {
        if (c + 1 < 4) { prefetch(c + 1, (c + 1) & 1); CP_WAIT1(); }
        else           { CP_WAIT0(); }
        __syncthreads();
        uint32_t base = ab + (c & 1) * 98304;
        #pragma unroll
        for (int ks = 0; ks < 4; ks++) {
            int kb = ks * 32;
            uint32_t Ah[2][4], Al[2][4];
            #pragma unroll
            for (int mf = 0; mf < 2; mf++) {
                uint32_t off = sw128((wm + mf * 16 + arow) * 128 + kb + ac16);
                ldsm4(Ah[mf][0], Ah[mf][1], Ah[mf][2], Ah[mf][3], base + off);
                ldsm4(Al[mf][0], Al[mf][1], Al[mf][2], Al[mf][3], base + 16384 + off);
            }
            #pragma unroll
            for (int g = 0; g < 4; g++) {
                uint32_t off = sw128((wn + g * 16 + brow) * 128 + kb + bc16);
                uint32_t h0, h1, h2, h3, q0, q1, q2, q3;
                ldsm4(h0, h1, h2, h3, base + 32768 + off);
                ldsm4(q0, q1, q2, q3, base + 65536 + off);
                uint32_t Bh0[2] = {h0, h1}, Bh1[2] = {h2, h3};
                uint32_t Bl0[2] = {q0, q1}, Bl1[2] = {q2, q3};
                #pragma unroll
                for (int mf = 0; mf < 2; mf++) {
                    mma16816(acc[mf][2*g],   Ah[mf], Bh0);
                    mma16816(acc[mf][2*g+1], Ah[mf], Bh1);
                    mma16816(acc[mf][2*g],   Al[mf], Bh0);
                    mma16816(acc[mf][2*g+1], Al[mf], Bh1);
                    mma16816(acc[mf][2*g],   Ah[mf], Bl0);
                    mma16816(acc[mf][2*g+1], Ah[mf], Bl1);
                }
            }
        }
        __syncthreads();
    }

    // ---- epilogue: bias, sj reduction, w, scale, transpose, store ----------
    #pragma unroll
    for (int nf = 0; nf < 8; nf++) {
        int c0 = wn + nf * 8 + 2 * (lane & 3);
        float b0 = rbs[c0], b1 = rbs[c0 + 1];
        #pragma unroll
        for (int mf = 0; mf < 2; mf++) {
            acc[mf][nf][0] += b0; acc[mf][nf][1] += b1;
            acc[mf][nf][2] += b0; acc[mf][nf][3] += b1;
        }
    }

    float p[2][2] = {};
    #pragma unroll
    for (int nf = 0; nf < 8; nf++) {
        int c0 = wn + nf * 8 + 2 * (lane & 3);
        float a0 = awjs[c0], a1 = awjs[c0 + 1];
        #pragma unroll
        for (int mf = 0; mf < 2; mf++) {
            p[mf][0] = fmaf(acc[mf][nf][0], a0, fmaf(acc[mf][nf][1], a1, p[mf][0]));
            p[mf][1] = fmaf(acc[mf][nf][2], a0, fmaf(acc[mf][nf][3], a1, p[mf][1]));
        }
    }
    #pragma unroll
    for (int mf = 0; mf < 2; mf++)
        #pragma unroll
        for (int q = 0; q < 2; q++) {
            p[mf][q] += __shfl_xor_sync(0xffffffffu, p[mf][q], 1);
            p[mf][q] += __shfl_xor_sync(0xffffffffu, p[mf][q], 2);
            if ((lane & 3) == 0)
                sjred[wid & 3][wm + mf * 16 + q * 8 + (lane >> 2)] = p[mf][q];
        }
    __syncthreads();

    if (tid < 128) {
        float s = sjred[0][tid] + sjred[1][tid] + sjred[2][tid] + sjred[3][tid];
        float w = __expf(s);
        wsm[tid] = w;
        g_w[br * Nn + n0 + tid] = w;
    }
    __syncthreads();

    // scale + fp16 convert into transpose smem: thf[d][m] (256 x 128 fp16)
    __half* thf = (__half*)abp;
    #pragma unroll
    for (int mf = 0; mf < 2; mf++)
        #pragma unroll
        for (int q = 0; q < 2; q++) {
            int row = wm + mf * 16 + q * 8 + (lane >> 2);
            float w = wsm[row];
            #pragma unroll
            for (int nf = 0; nf < 8; nf++) {
                int c0 = wn + nf * 8 + 2 * (lane & 3);
                thf[c0 * 128 + row]       = __float2half(acc[mf][nf][2 * q] * w);
                thf[(c0 + 1) * 128 + row] = __float2half(acc[mf][nf][2 * q + 1] * w);
            }
        }
    __syncthreads();

    // coalesced writes: 256 d-rows x 128 m fp16
    for (int it = 0; it < 4; it++) {
        int idx = it * 512 + tid;          // 0..2047
        int d = idx >> 3, mq = idx & 7;
        size_t go = ((size_t)br * DOUT + d) * Nn + n0 + mq * 16;
        *(uint4*)&g_wff[go]     = *(uint4*)&thf[d * 128 + mq * 16];
        *(uint4*)&g_wff[go + 8] = *(uint4*)&thf[d * 128 + mq * 16 + 8];
    }
}

// ---------------------------------------------------------------------------
// prepass: adj int32 -> fp16 {0,1}; invZ[br,n] = 1 / sum_m adj[n,m]*w[m]
// ---------------------------------------------------------------------------
__global__ __launch_bounds__(256) void prepass_kernel(const int* __restrict__ adj) {
    __shared__ float ws[Nn];
    const int tid = threadIdx.x, wid = tid >> 5, lane = tid & 31;
    const int br = blockIdx.x >> 5, nb = blockIdx.x & 31;
    for (int i = tid; i < Nn; i += 256) ws[i] = g_w[br * Nn + i];
    __syncthreads();

    #pragma unroll
    for (int i = 0; i < 4; i++) {
        int n = nb * 32 + wid * 4 + i;
        const int4* arow = (const int4*)(adj + (((size_t)br << 10) + n) * Nn);
        __half* brow = g_adjh + (((size_t)br << 10) + n) * Nn;
        float z = 0.f;
        #pragma unroll
        for (int k = 0; k < 8; k++) {
            int m = k * 128 + lane * 4;
            int4 a = arow[k * 32 + lane];
            uint2 o;
            o.x = (a.x ? 0x3C00u : 0u) | ((a.y ? 0x3C00u : 0u) << 16);
            o.y = (a.z ? 0x3C00u : 0u) | ((a.w ? 0x3C00u : 0u) << 16);
            *(uint2*)(brow + m) = o;
            if (a.x) z += ws[m];
            if (a.y) z += ws[m + 1];
            if (a.z) z += ws[m + 2];
            if (a.w) z += ws[m + 3];
        }
        #pragma unroll
        for (int o = 16; o; o >>= 1) z += __shfl_xor_sync(0xffffffffu, z, o);
        if (lane == 0) g_invZ[(br << 10) + n] = 1.0f / z;
    }
}

// ---------------------------------------------------------------------------
// agg via fp16 mma.sync (single term):
//   out[b,n,d] = sum_r invZ[r,n] * (adj_r @ wf_r^T)[n,d]
// CTA tile 128n x 128d; 32 super-chunks of K=128 (2 sub-chunks of 64).
// 8 warps 2x4, warp tile 64x32. grid (2, 8, 8).
// stage: 2 x (A 16KB | B 16KB) = 64KB, double buffered = 128KB.
// ---------------------------------------------------------------------------
#define A_SMEM (1024 + 2 * 65536)
__global__ __launch_bounds__(256) void agg_mma_kernel(float* __restrict__ out) {
    extern __shared__ char smem[];
    __shared__ float izs[Rr * 128];
    const uint32_t ab = (smem_u32(smem) + 1023) & ~1023u;
    const int tid = threadIdx.x, wid = tid >> 5, lane = tid & 31;
    const int d0 = blockIdx.x * 128;
    const int n0 = blockIdx.y * 128;
    const int b  = blockIdx.z;
    const int wm = (wid >> 2) * 64, wn = (wid & 3) * 32;

    for (int i = tid; i < Rr * 128; i += 256)
        izs[i] = g_invZ[((b * Rr + (i >> 7)) << 10) + n0 + (i & 127)];

    auto prefetch = [&](int sc, int stage) {
        uint32_t sbase = ab + stage * 65536;
        #pragma unroll
        for (int cc = 0; cc < 2; cc++) {
            int c = sc * 2 + cc;
            int r = c >> 4, kc = c & 15, m0 = kc * 64;
            uint32_t base = sbase + cc * 32768;
            size_t brr = (size_t)(b * Rr + r);
            for (int u = tid; u < 2048; u += 256) {
                int t = u >> 10, v = u & 1023, row = v >> 3, un = v & 7;
                uint32_t dst = base + t * 16384 + sw128(row * 128 + un * 16);
                const __half* src;
                if (t == 0) src = g_adjh + (brr * Nn + n0 + row) * Nn + m0 + un * 8;
                else        src = g_wff  + (brr * DOUT + d0 + row) * Nn + m0 + un * 8;
                CP_ASYNC16(dst, (const char*)src);
            }
        }
        CP_COMMIT();
    };

    float total[4][4][4] = {};
    float acc[4][4][4] = {};
    const int grp = lane >> 3, l7 = lane & 7;
    const int arow = (grp & 1) * 8 + l7, ac16 = (grp >> 1) * 16;
    const int brow = (grp >> 1) * 8 + l7, bc16 = (grp & 1) * 16;
    const int SC = 32;

    prefetch(0, 0);
    for (int sc = 0; sc < SC; sc++) {
        if (sc + 1 < SC) { prefetch(sc + 1, (sc + 1) & 1); CP_WAIT1(); }
        else             { CP_WAIT0(); }
        __syncthreads();
        uint32_t sbase = ab + (sc & 1) * 65536;
        #pragma unroll
        for (int cc = 0; cc < 2; cc++) {
            uint32_t base = sbase + cc * 32768;
            #pragma unroll
            for (int ks = 0; ks < 4; ks++) {
                int kb = ks * 32;
                uint32_t A[4][4], Bf[4][2];
                #pragma unroll
                for (int mf = 0; mf < 4; mf++) {
                    uint32_t off = sw128((wm + mf * 16 + arow) * 128 + kb + ac16);
                    ldsm4(A[mf][0], A[mf][1], A[mf][2], A[mf][3], base + off);
                }
                #pragma unroll
                for (int g = 0; g < 2; g++) {
                    uint32_t off = sw128((wn + g * 16 + brow) * 128 + kb + bc16);
                    uint32_t t0, t1, t2, t3;
                    ldsm4(t0, t1, t2, t3, base + 16384 + off);
                    Bf[2*g][0] = t0; Bf[2*g][1] = t1; Bf[2*g+1][0] = t2; Bf[2*g+1][1] = t3;
                }
                #pragma unroll
                for (int mf = 0; mf < 4; mf++)
                    #pragma unroll
                    for (int nf = 0; nf < 4; nf++)
                        mma16816h(acc[mf][nf], A[mf], Bf[nf]);
            }
        }
        __syncthreads();

        if ((sc & 7) == 7) {             // end of relation r: fold with invZ
            int r = sc >> 3;
            #pragma unroll
            for (int mf = 0; mf < 4; mf++) {
                float iz0 = izs[r * 128 + wm + mf * 16 + (lane >> 2)];
                float iz1 = izs[r * 128 + wm + mf * 16 + (lane >> 2) + 8];
                #pragma unroll
                for (int nf = 0; nf < 4; nf++) {
                    total[mf][nf][0] = fmaf(iz0, acc[mf][nf][0], total[mf][nf][0]);
                    total[mf][nf][1] = fmaf(iz0, acc[mf][nf][1], total[mf][nf][1]);
                    total[mf][nf][2] = fmaf(iz1, acc[mf][nf][2], total[mf][nf][2]);
                    total[mf][nf][3] = fmaf(iz1, acc[mf][nf][3], total[mf][nf][3]);
                    acc[mf][nf][0] = 0.f; acc[mf][nf][1] = 0.f;
                    acc[mf][nf][2] = 0.f; acc[mf][nf][3] = 0.f;
                }
            }
        }
    }

    #pragma unroll
    for (int nf = 0; nf < 4; nf++) {
        int col = d0 + wn + nf * 8 + 2 * (lane & 3);
        #pragma unroll
        for (int mf = 0; mf < 4; mf++) {
            int row = n0 + wm + mf * 16 + (lane >> 2);
            float* p0 = out + ((size_t)b * Nn + row) * DOUT + col;
            float* p1 = out + ((size_t)b * Nn + row + 8) * DOUT + col;
            p0[0] = total[mf][nf][0]; p0[1] = total[mf][nf][1];
            p1[0] = total[mf][nf][2]; p1[1] = total[mf][nf][3];
        }
    }
}

// ---------------------------------------------------------------------------
// gate epilogue: out = sigmoid(out . gw + gb) * out, one block per (b,n)
// ---------------------------------------------------------------------------
__global__ __launch_bounds__(256) void gate_kernel(
    float* __restrict__ out, const float* __restrict__ gw,
    const float* __restrict__ gb_p)
{
    __shared__ float red[8];
    float* o = out + (size_t)blockIdx.x * DOUT;
    int t = threadIdx.x, lane = t & 31;
    float a = o[t];
    float v = a * gw[t];
    #pragma unroll
    for (int off = 16; off; off >>= 1) v += __shfl_xor_sync(0xffffffffu, v, off);
    if (lane == 0) red[t >> 5] = v;
    __syncthreads();
    if (t < 32) {
        float r = (t < 8) ? red[t] : 0.0f;
        #pragma unroll
        for (int off = 4; off; off >>= 1) r += __shfl_xor_sync(0xffffffffu, r, off);
        if (t == 0) red[0] = r;
    }
    __syncthreads();
    float g = 1.0f / (1.0f + __expf(-(red[0] + gb_p[0])));
    o[t] = g * a;
}

// ---------------------------------------------------------------------------
extern "C" void kernel_launch(void* const* d_in, const int* in_sizes, int n_in,
                              void* d_out, int out_size)
{
    const float* x   = (const float*)d_in[0];
    const int*   adj = (const int*)  d_in[1];
    const float* rw  = (const float*)d_in[2];
    const float* rb  = (const float*)d_in[3];
    const float* aw  = (const float*)d_in[4];
    const float* gw  = (const float*)d_in[6];
    const float* gb  = (const float*)d_in[7];
    float* out = (float*)d_out;

    cudaFuncSetAttribute(fw_kernel,
                         cudaFuncAttributeMaxDynamicSharedMemorySize, FW_SMEM);
    cudaFuncSetAttribute(agg_mma_kernel,
                         cudaFuncAttributeMaxDynamicSharedMemorySize, A_SMEM);

    conv_x_kernel<<<(Bq * Nn * DIN / 4) / 256, 256>>>(x);
    conv_rw_kernel<<<(Rr * DOUT * DIN / 4) / 256, 256>>>(rw);

    fw_kernel<<<dim3(8, Bq * Rr), 512, FW_SMEM>>>(rb, aw);

    prepass_kernel<<<Bq * Rr * 32, 256>>>(adj);

    agg_mma_kernel<<<dim3(2, 8, Bq), 256, A_SMEM>>>(out);

    gate_kernel<<<Bq * Nn, 256>>>(out, gw, gb);
}

// round 8
// speedup vs baseline: 1.8126x; 1.1588x over previous
#include <cuda_runtime.h>
#include <cuda_fp16.h>
#include <cstdint>

#define Bq   8
#define Nn   1024
#define DIN  256
#define DOUT 256
#define Rr   4

// ------------------------- scratch globals ----------------------------------
__device__ __half g_xf[(size_t)Bq * Nn * DIN];
__device__ __half g_rwhf[(size_t)Rr * DOUT * DIN];
__device__ __half g_rwlf[(size_t)Rr * DOUT * DIN];
__device__ float  g_w[Bq * Rr * Nn];
__device__ float  g_invZ[Bq * Rr * Nn];
__device__ __half g_wff[(size_t)Bq * Rr * DOUT * Nn];      // wf^T fp16 [br][d][m]
__device__ __half g_adjh[(size_t)Bq * Rr * Nn * Nn];       // 64 MB fp16 {0,1}

// ------------------------- helpers ------------------------------------------
__device__ __forceinline__ uint32_t smem_u32(const void* p) {
    uint32_t a;
    asm("{ .reg .u64 t; cvta.to.shared.u64 t, %1; cvt.u32.u64 %0, t; }"
        : "=r"(a) : "l"(p));
    return a;
}
#define CP_ASYNC16(dst, src) asm volatile("cp.async.cg.shared.global [%0], [%1], 16;" :: "r"(dst), "l"(src))
#define CP_COMMIT()          asm volatile("cp.async.commit_group;" ::: "memory")
#define CP_WAIT1()           asm volatile("cp.async.wait_group 1;" ::: "memory")
#define CP_WAIT0()           asm volatile("cp.async.wait_group 0;" ::: "memory")

__device__ __forceinline__ uint32_t sw128(uint32_t off) {
    return off ^ ((off >> 3) & 0x70);
}
__device__ __forceinline__ void ldsm4(uint32_t& r0, uint32_t& r1,
                                      uint32_t& r2, uint32_t& r3, uint32_t a) {
    asm volatile("ldmatrix.sync.aligned.m8n8.x4.shared.b16 {%0,%1,%2,%3}, [%4];"
                 : "=r"(r0), "=r"(r1), "=r"(r2), "=r"(r3) : "r"(a));
}
__device__ __forceinline__ void mma16816h(float* c, const uint32_t* a,
                                          const uint32_t* b) {
    asm volatile("mma.sync.aligned.m16n8k16.row.col.f32.f16.f16.f32 "
        "{%0,%1,%2,%3}, {%4,%5,%6,%7}, {%8,%9}, {%0,%1,%2,%3};"
        : "+f"(c[0]), "+f"(c[1]), "+f"(c[2]), "+f"(c[3])
        : "r"(a[0]), "r"(a[1]), "r"(a[2]), "r"(a[3]), "r"(b[0]), "r"(b[1]));
}
__device__ __forceinline__ void hsplit(float v, __half& h, __half& l) {
    h = __float2half_rn(v);
    l = __float2half_rn(v - __half2float(h));
}
__device__ __forceinline__ uint32_t pack_h2(__half a, __half b) {
    return (uint32_t)__half_as_ushort(a) | ((uint32_t)__half_as_ushort(b) << 16);
}

// ---------------------------------------------------------------------------
// conversions
// ---------------------------------------------------------------------------
__global__ __launch_bounds__(256) void conv_x_kernel(const float* __restrict__ x) {
    size_t i = (size_t)blockIdx.x * 256 + threadIdx.x;
    float4 v = ((const float4*)x)[i];
    uint2 H;
    H.x = pack_h2(__float2half_rn(v.x), __float2half_rn(v.y));
    H.y = pack_h2(__float2half_rn(v.z), __float2half_rn(v.w));
    *(uint2*)&g_xf[4 * i] = H;
}
__global__ __launch_bounds__(256) void conv_rw_kernel(const float* __restrict__ rw) {
    size_t i = (size_t)blockIdx.x * 256 + threadIdx.x;
    float4 v = ((const float4*)rw)[i];
    __half h0, h1, h2, h3, l0, l1, l2, l3;
    hsplit(v.x, h0, l0); hsplit(v.y, h1, l1);
    hsplit(v.z, h2, l2); hsplit(v.w, h3, l3);
    uint2 H, L;
    H.x = pack_h2(h0, h1); H.y = pack_h2(h2, h3);
    L.x = pack_h2(l0, l1); L.y = pack_h2(l2, l3);
    *(uint2*)&g_rwhf[4 * i] = H;
    *(uint2*)&g_rwlf[4 * i] = L;
}

// ---------------------------------------------------------------------------
// FUSED feats+wf kernel (2-term fp16: x single, rw hi/lo):
//   feats[n,d] = sum_k x[n,k]*rw[d,k] + rb[d]
//   sj[n] = feats[n,:] . attn_w[256:]; w = exp(sj)
//   wf^T[d,m] = fp16(w[m] * feats[m,d]), coalesced writes
// CTA: 128n x 256d, K=256 in 4 chunks of 64, double buffered.
// 512 threads = 16 warps (4m x 4n), warp tile 32n x 64d.
// stage: A 16KB | Bh 32KB | Bl 32KB = 80KB, x2 = 160KB dynamic.
// ---------------------------------------------------------------------------
#define FW_SMEM (1024 + 2 * 81920)
__global__ __launch_bounds__(512, 1) void fw_kernel(
    const float* __restrict__ rb, const float* __restrict__ aw)
{
    extern __shared__ char smem[];
    __shared__ float awjs[256];
    __shared__ float rbs[256];
    __shared__ float sjred[4][128];
    __shared__ float wsm[128];
    char* abp = (char*)(((uintptr_t)smem + 1023) & ~(uintptr_t)1023);
    const uint32_t ab = (smem_u32(smem) + 1023) & ~1023u;
    const int tid = threadIdx.x, wid = tid >> 5, lane = tid & 31;
    const int n0 = blockIdx.x * 128;
    const int br = blockIdx.y, b = br >> 2, r = br & 3;
    const int wm = (wid >> 2) * 32, wn = (wid & 3) * 64;

    if (tid < 256) { awjs[tid] = aw[DOUT + tid]; rbs[tid] = rb[r * DOUT + tid]; }

    auto prefetch = [&](int c, int stage) {
        uint32_t base = ab + stage * 81920;
        for (int u = tid; u < 5120; u += 512) {
            uint32_t dst;
            const __half* src;
            if (u < 1024) {           // A: 128 rows x 64 k fp16
                int row = u >> 3, un = u & 7;
                dst = base + sw128(row * 128 + un * 16);
                src = g_xf + (size_t)b * (Nn * DIN) + (size_t)(n0 + row) * DIN
                    + c * 64 + un * 8;
            } else {                  // Bh | Bl: 256 rows x 64 k
                int v2 = u - 1024;
                int t = v2 >> 11, v = v2 & 2047, row = v >> 3, un = v & 7;
                dst = base + 16384 + t * 32768 + sw128(row * 128 + un * 16);
                src = (t ? g_rwlf : g_rwhf)
                    + (size_t)r * (DOUT * DIN) + (size_t)row * DIN + c * 64 + un * 8;
            }
            CP_ASYNC16(dst, (const char*)src);
        }
        CP_COMMIT();
    };

    float acc[2][8][4] = {};
    const int grp = lane >> 3, l7 = lane & 7;
    const int arow = (grp & 1) * 8 + l7, ac16 = (grp >> 1) * 16;
    const int brow = (grp >> 1) * 8 + l7, bc16 = (grp & 1) * 16;

    prefetch(0, 0);
    for (int c = 0; c < 4; c++) {
        if (c + 1 < 4) { prefetch(c + 1, (c + 1) & 1); CP_WAIT1(); }
        else           { CP_WAIT0(); }
        __syncthreads();
        uint32_t base = ab + (c & 1) * 81920;
        #pragma unroll
        for (int ks = 0; ks < 4; ks++) {
            int kb = ks * 32;
            uint32_t Ax[2][4];
            #pragma unroll
            for (int mf = 0; mf < 2; mf++) {
                uint32_t off = sw128((wm + mf * 16 + arow) * 128 + kb + ac16);
                ldsm4(Ax[mf][0], Ax[mf][1], Ax[mf][2], Ax[mf][3], base + off);
            }
            #pragma unroll
            for (int g = 0; g < 4; g++) {
                uint32_t off = sw128((wn + g * 16 + brow) * 128 + kb + bc16);
                uint32_t h0, h1, h2, h3, q0, q1, q2, q3;
                ldsm4(h0, h1, h2, h3, base + 16384 + off);
                ldsm4(q0, q1, q2, q3, base + 49152 + off);
                uint32_t Bh0[2] = {h0, h1}, Bh1[2] = {h2, h3};
                uint32_t Bl0[2] = {q0, q1}, Bl1[2] = {q2, q3};
                #pragma unroll
                for (int mf = 0; mf < 2; mf++) {
                    mma16816h(acc[mf][2*g],   Ax[mf], Bh0);
                    mma16816h(acc[mf][2*g+1], Ax[mf], Bh1);
                    mma16816h(acc[mf][2*g],   Ax[mf], Bl0);
                    mma16816h(acc[mf][2*g+1], Ax[mf], Bl1);
                }
            }
        }
        __syncthreads();
    }

    // ---- epilogue: bias, sj reduction, w, scale, transpose, store ----------
    #pragma unroll
    for (int nf = 0; nf < 8; nf++) {
        int c0 = wn + nf * 8 + 2 * (lane & 3);
        float b0 = rbs[c0], b1 = rbs[c0 + 1];
        #pragma unroll
        for (int mf = 0; mf < 2; mf++) {
            acc[mf][nf][0] += b0; acc[mf][nf][1] += b1;
            acc[mf][nf][2] += b0; acc[mf][nf][3] += b1;
        }
    }

    float p[2][2] = {};
    #pragma unroll
    for (int nf = 0; nf < 8; nf++) {
        int c0 = wn + nf * 8 + 2 * (lane & 3);
        float a0 = awjs[c0], a1 = awjs[c0 + 1];
        #pragma unroll
        for (int mf = 0; mf < 2; mf++) {
            p[mf][0] = fmaf(acc[mf][nf][0], a0, fmaf(acc[mf][nf][1], a1, p[mf][0]));
            p[mf][1] = fmaf(acc[mf][nf][2], a0, fmaf(acc[mf][nf][3], a1, p[mf][1]));
        }
    }
    #pragma unroll
    for (int mf = 0; mf < 2; mf++)
        #pragma unroll
        for (int q = 0; q < 2; q++) {
            p[mf][q] += __shfl_xor_sync(0xffffffffu, p[mf][q], 1);
            p[mf][q] += __shfl_xor_sync(0xffffffffu, p[mf][q], 2);
            if ((lane & 3) == 0)
                sjred[wid & 3][wm + mf * 16 + q * 8 + (lane >> 2)] = p[mf][q];
        }
    __syncthreads();

    if (tid < 128) {
        float s = sjred[0][tid] + sjred[1][tid] + sjred[2][tid] + sjred[3][tid];
        float w = __expf(s);
        wsm[tid] = w;
        g_w[br * Nn + n0 + tid] = w;
    }
    __syncthreads();

    __half* thf = (__half*)abp;      // 256 d x 128 m fp16 = 64KB (reuse stage)
    #pragma unroll
    for (int mf = 0; mf < 2; mf++)
        #pragma unroll
        for (int q = 0; q < 2; q++) {
            int row = wm + mf * 16 + q * 8 + (lane >> 2);
            float w = wsm[row];
            #pragma unroll
            for (int nf = 0; nf < 8; nf++) {
                int c0 = wn + nf * 8 + 2 * (lane & 3);
                thf[c0 * 128 + row]       = __float2half(acc[mf][nf][2 * q] * w);
                thf[(c0 + 1) * 128 + row] = __float2half(acc[mf][nf][2 * q + 1] * w);
            }
        }
    __syncthreads();

    for (int it = 0; it < 4; it++) {
        int idx = it * 512 + tid;          // 0..2047
        int d = idx >> 3, mq = idx & 7;
        size_t go = ((size_t)br * DOUT + d) * Nn + n0 + mq * 16;
        *(uint4*)&g_wff[go]     = *(uint4*)&thf[d * 128 + mq * 16];
        *(uint4*)&g_wff[go + 8] = *(uint4*)&thf[d * 128 + mq * 16 + 8];
    }
}

// ---------------------------------------------------------------------------
// prepass: adj int32 -> fp16 {0,1}; invZ[br,n] = 1 / sum_m adj[n,m]*w[m]
// ---------------------------------------------------------------------------
__global__ __launch_bounds__(256) void prepass_kernel(const int* __restrict__ adj) {
    __shared__ float ws[Nn];
    const int tid = threadIdx.x, wid = tid >> 5, lane = tid & 31;
    const int br = blockIdx.x >> 5, nb = blockIdx.x & 31;
    for (int i = tid; i < Nn; i += 256) ws[i] = g_w[br * Nn + i];
    __syncthreads();

    #pragma unroll
    for (int i = 0; i < 4; i++) {
        int n = nb * 32 + wid * 4 + i;
        const int4* arow = (const int4*)(adj + (((size_t)br << 10) + n) * Nn);
        __half* brow = g_adjh + (((size_t)br << 10) + n) * Nn;
        float z = 0.f;
        #pragma unroll
        for (int k = 0; k < 8; k++) {
            int m = k * 128 + lane * 4;
            int4 a = arow[k * 32 + lane];
            uint2 o;
            o.x = (a.x ? 0x3C00u : 0u) | ((a.y ? 0x3C00u : 0u) << 16);
            o.y = (a.z ? 0x3C00u : 0u) | ((a.w ? 0x3C00u : 0u) << 16);
            *(uint2*)(brow + m) = o;
            if (a.x) z += ws[m];
            if (a.y) z += ws[m + 1];
            if (a.z) z += ws[m + 2];
            if (a.w) z += ws[m + 3];
        }
        #pragma unroll
        for (int o = 16; o; o >>= 1) z += __shfl_xor_sync(0xffffffffu, z, o);
        if (lane == 0) g_invZ[(br << 10) + n] = 1.0f / z;
    }
}

// ---------------------------------------------------------------------------
// agg via fp16 mma.sync: out[b,n,d] = sum_r invZ[r,n] * (adj_r @ wf_r^T)[n,d]
// CTA tile 64n x 128d; 32 super-chunks of K=128 (2 sub-chunks of 64).
// 8 warps 2x4, warp tile 32n x 32d. grid (2, 16, 8) = 256 CTAs, 2 CTA/SM.
// stage: 2 x (A 8KB | B 16KB) = 48KB, double buffered = 96KB.
// ---------------------------------------------------------------------------
#define A_SMEM (1024 + 2 * 49152)
__global__ __launch_bounds__(256, 2) void agg_mma_kernel(float* __restrict__ out) {
    extern __shared__ char smem[];
    __shared__ float izs[Rr * 64];
    const uint32_t ab = (smem_u32(smem) + 1023) & ~1023u;
    const int tid = threadIdx.x, wid = tid >> 5, lane = tid & 31;
    const int d0 = blockIdx.x * 128;
    const int n0 = blockIdx.y * 64;
    const int b  = blockIdx.z;
    const int wm = (wid >> 2) * 32, wn = (wid & 3) * 32;

    if (tid < Rr * 64)
        izs[tid] = g_invZ[((b * Rr + (tid >> 6)) << 10) + n0 + (tid & 63)];

    auto prefetch = [&](int sc, int stage) {
        uint32_t sbase = ab + stage * 49152;
        #pragma unroll
        for (int cc = 0; cc < 2; cc++) {
            int c = sc * 2 + cc;
            int r = c >> 4, kc = c & 15, m0 = kc * 64;
            uint32_t base = sbase + cc * 24576;
            size_t brr = (size_t)(b * Rr + r);
            for (int u = tid; u < 1536; u += 256) {
                uint32_t dst;
                const __half* src;
                if (u < 512) {        // A: 64 rows x 64 m
                    int row = u >> 3, un = u & 7;
                    dst = base + sw128(row * 128 + un * 16);
                    src = g_adjh + (brr * Nn + n0 + row) * Nn + m0 + un * 8;
                } else {              // B: 128 rows x 64 m
                    int v = u - 512;
                    int row = v >> 3, un = v & 7;
                    dst = base + 8192 + sw128(row * 128 + un * 16);
                    src = g_wff + (brr * DOUT + d0 + row) * Nn + m0 + un * 8;
                }
                CP_ASYNC16(dst, (const char*)src);
            }
        }
        CP_COMMIT();
    };

    float total[2][4][4] = {};
    float acc[2][4][4] = {};
    const int grp = lane >> 3, l7 = lane & 7;
    const int arow = (grp & 1) * 8 + l7, ac16 = (grp >> 1) * 16;
    const int brow = (grp >> 1) * 8 + l7, bc16 = (grp & 1) * 16;
    const int SC = 32;

    prefetch(0, 0);
    for (int sc = 0; sc < SC; sc++) {
        if (sc + 1 < SC) { prefetch(sc + 1, (sc + 1) & 1); CP_WAIT1(); }
        else             { CP_WAIT0(); }
        __syncthreads();
        uint32_t sbase = ab + (sc & 1) * 49152;
        #pragma unroll
        for (int cc = 0; cc < 2; cc++) {
            uint32_t base = sbase + cc * 24576;
            #pragma unroll
            for (int ks = 0; ks < 4; ks++) {
                int kb = ks * 32;
                uint32_t A[2][4], Bf[4][2];
                #pragma unroll
                for (int mf = 0; mf < 2; mf++) {
                    uint32_t off = sw128((wm + mf * 16 + arow) * 128 + kb + ac16);
                    ldsm4(A[mf][0], A[mf][1], A[mf][2], A[mf][3], base + off);
                }
                #pragma unroll
                for (int g = 0; g < 2; g++) {
                    uint32_t off = sw128((wn + g * 16 + brow) * 128 + kb + bc16);
                    uint32_t t0, t1, t2, t3;
                    ldsm4(t0, t1, t2, t3, base + 8192 + off);
                    Bf[2*g][0] = t0; Bf[2*g][1] = t1;
                    Bf[2*g+1][0] = t2; Bf[2*g+1][1] = t3;
                }
                #pragma unroll
                for (int mf = 0; mf < 2; mf++)
                    #pragma unroll
                    for (int nf = 0; nf < 4; nf++)
                        mma16816h(acc[mf][nf], A[mf], Bf[nf]);
            }
        }
        __syncthreads();

        if ((sc & 7) == 7) {             // end of relation r: fold with invZ
            int r = sc >> 3;
            #pragma unroll
            for (int mf = 0; mf < 2; mf++) {
                float iz0 = izs[r * 64 + wm + mf * 16 + (lane >> 2)];
                float iz1 = izs[r * 64 + wm + mf * 16 + (lane >> 2) + 8];
                #pragma unroll
                for (int nf = 0; nf < 4; nf++) {
                    total[mf][nf][0] = fmaf(iz0, acc[mf][nf][0], total[mf][nf][0]);
                    total[mf][nf][1] = fmaf(iz0, acc[mf][nf][1], total[mf][nf][1]);
                    total[mf][nf][2] = fmaf(iz1, acc[mf][nf][2], total[mf][nf][2]);
                    total[mf][nf][3] = fmaf(iz1, acc[mf][nf][3], total[mf][nf][3]);
                    acc[mf][nf][0] = 0.f; acc[mf][nf][1] = 0.f;
                    acc[mf][nf][2] = 0.f; acc[mf][nf][3] = 0.f;
                }
            }
        }
    }

    #pragma unroll
    for (int nf = 0; nf < 4; nf++) {
        int col = d0 + wn + nf * 8 + 2 * (lane & 3);
        #pragma unroll
        for (int mf = 0; mf < 2; mf++) {
            int row = n0 + wm + mf * 16 + (lane >> 2);
            float* p0 = out + ((size_t)b * Nn + row) * DOUT + col;
            float* p1 = out + ((size_t)b * Nn + row + 8) * DOUT + col;
            p0[0] = total[mf][nf][0]; p0[1] = total[mf][nf][1];
            p1[0] = total[mf][nf][2]; p1[1] = total[mf][nf][3];
        }
    }
}

// ---------------------------------------------------------------------------
// gate epilogue: out = sigmoid(out . gw + gb) * out, one block per (b,n)
// ---------------------------------------------------------------------------
__global__ __launch_bounds__(256) void gate_kernel(
    float* __restrict__ out, const float* __restrict__ gw,
    const float* __restrict__ gb_p)
{
    __shared__ float red[8];
    float* o = out + (size_t)blockIdx.x * DOUT;
    int t = threadIdx.x, lane = t & 31;
    float a = o[t];
    float v = a * gw[t];
    #pragma unroll
    for (int off = 16; off; off >>= 1) v += __shfl_xor_sync(0xffffffffu, v, off);
    if (lane == 0) red[t >> 5] = v;
    __syncthreads();
    if (t < 32) {
        float r = (t < 8) ? red[t] : 0.0f;
        #pragma unroll
        for (int off = 4; off; off >>= 1) r += __shfl_xor_sync(0xffffffffu, r, off);
        if (t == 0) red[0] = r;
    }
    __syncthreads();
    float g = 1.0f / (1.0f + __expf(-(red[0] + gb_p[0])));
    o[t] = g * a;
}

// ---------------------------------------------------------------------------
extern "C" void kernel_launch(void* const* d_in, const int* in_sizes, int n_in,
                              void* d_out, int out_size)
{
    const float* x   = (const float*)d_in[0];
    const int*   adj = (const int*)  d_in[1];
    const float* rw  = (const float*)d_in[2];
    const float* rb  = (const float*)d_in[3];
    const float* aw  = (const float*)d_in[4];
    const float* gw  = (const float*)d_in[6];
    const float* gb  = (const float*)d_in[7];
    float* out = (float*)d_out;

    cudaFuncSetAttribute(fw_kernel,
                         cudaFuncAttributeMaxDynamicSharedMemorySize, FW_SMEM);
    cudaFuncSetAttribute(agg_mma_kernel,
                         cudaFuncAttributeMaxDynamicSharedMemorySize, A_SMEM);

    conv_x_kernel<<<(Bq * Nn * DIN / 4) / 256, 256>>>(x);
    conv_rw_kernel<<<(Rr * DOUT * DIN / 4) / 256, 256>>>(rw);

    fw_kernel<<<dim3(8, Bq * Rr), 512, FW_SMEM>>>(rb, aw);

    prepass_kernel<<<Bq * Rr * 32, 256>>>(adj);

    agg_mma_kernel<<<dim3(2, 16, Bq), 256, A_SMEM>>>(out);

    gate_kernel<<<Bq * Nn, 256>>>(out, gw, gb);
}